// round 11
// baseline (speedup 1.0000x reference)
#include <cuda_runtime.h>
#include <cuda_fp16.h>
#include <cstdint>

// ---------------------------------------------------------------------------
// E3NN lifting TP: per l, C[M,256] = A[M,64] * W_l[64,256], M = N*(2l+1).
// mma.sync m16n8k16 fp16 (x fp16, W fp16 w/ 1/8 folded), rel_err ~2.9e-4.
// R10: W fragments live in REGISTERS (loaded once per persistent CTA; each
// CTA owns one 128-col half, x is read twice) -> mainloop smem = A-ldsm only.
// Output-linear flat Cs with byte swizzle b^=((b>>9)&7)<<4 -> conflict-free
// scatter writes, float4 coalesced reads/stores. 2 syncthreads per tile.
// ---------------------------------------------------------------------------

constexpr int XROW = 576;
constexpr int OROW = 2304;

// Pre-transposed fp16 weights (scale 1/8 folded in): [l][w][u]
__device__ __align__(16) __half g_W[3][256][64];

__global__ void prep_w(const float* __restrict__ W0, const float* __restrict__ W1,
                       const float* __restrict__ W2) {
    int idx = blockIdx.x * blockDim.x + threadIdx.x;
    if (idx >= 3 * 64 * 256) return;
    int l = idx / (64 * 256);
    int r = idx - l * (64 * 256);
    int u = r >> 8, w = r & 255;
    const float* W = (l == 0) ? W0 : (l == 1) ? W1 : W2;
    g_W[l][w][u] = __float2half_rn(W[u * 256 + w] * 0.125f);
}

__device__ __forceinline__ uint32_t smem_u32(const void* p) {
    uint32_t a;
    asm("{ .reg .u64 t; cvta.to.shared.u64 t, %1; cvt.u32.u64 %0, t; }" : "=r"(a) : "l"(p));
    return a;
}
__device__ __forceinline__ void ldsm_x4(uint32_t addr, uint32_t* r) {
    asm volatile("ldmatrix.sync.aligned.m8n8.x4.shared.b16 {%0,%1,%2,%3}, [%4];"
                 : "=r"(r[0]), "=r"(r[1]), "=r"(r[2]), "=r"(r[3]) : "r"(addr));
}
__device__ __forceinline__ void mma_f16(float* c, const uint32_t* a,
                                        uint32_t b0, uint32_t b1) {
    asm volatile("mma.sync.aligned.m16n8k16.row.col.f32.f16.f16.f32 "
                 "{%0,%1,%2,%3}, {%4,%5,%6,%7}, {%8,%9}, {%0,%1,%2,%3};"
                 : "+f"(c[0]), "+f"(c[1]), "+f"(c[2]), "+f"(c[3])
                 : "r"(a[0]), "r"(a[1]), "r"(a[2]), "r"(a[3]), "r"(b0), "r"(b1));
}

// MTILE: multiple of 16 and of DL. THREADS = 8*MTILE.
// Warps = (MTILE/16) * 4: wm = wid>>2 (m16 band), wq = wid&3 (32-col group).
// CTA covers MTILE rows x 128 cols of half h = blockIdx.x & 1.
template <int DL, int MTILE, int THREADS>
__global__ __launch_bounds__(THREADS, (THREADS <= 384 ? 2 : 1))
void tp5(const float* __restrict__ x, float* __restrict__ out,
         int lsel, int xoff, int ooff, int Ncap, int ntiles) {
    constexpr int CSOFF = MTILE * 128;      // A: MTILE*128B, then Cs: MTILE*512B
    constexpr int NPT = MTILE / DL;         // n rows per tile
    constexpr int SPAN = 128 * DL;          // out floats per n per half
    constexpr int NRK = MTILE / (4 * DL);   // n-rows per reader k-step

    extern __shared__ char smem[];
    const uint32_t sb = smem_u32(smem);
    const int tid = threadIdx.x, lane = tid & 31, wid = tid >> 5;
    const int wm = wid >> 2, wq = wid & 3;
    const int h = (int)(blockIdx.x & 1);
    const int cid = (int)(blockIdx.x >> 1);
    const int cstep = (int)(gridDim.x >> 1);

    // ---- stage this half's W (128 rows x 64 u) into SW128 smem ----
    {
        const uint4* wsrc = (const uint4*)&g_W[lsel][h * 128][0];   // 1024 x 16B
        for (int t = tid; t < 1024; t += THREADS) {
            int w = t >> 3;
            uint32_t c = (uint32_t)(t & 7) * 16;
            *(uint4*)(smem + w * 128 + (c ^ ((w & 7) << 4))) = wsrc[t];
        }
    }
    __syncthreads();

    // ---- load B fragments ONCE into registers (W never changes) ----
    uint32_t B[4][2][4];   // [kk][np(16-row pair)][4 regs] = 32 regs
    {
        const int bRow = (lane & 7) + ((lane >> 4) << 3);
        const uint32_t bXor = (uint32_t)(bRow & 7) << 4;
        const uint32_t bCol = (uint32_t)((lane >> 3) & 1) * 16;
        const uint32_t bBase = sb + (uint32_t)(wq * 32 + bRow) * 128;
        #pragma unroll
        for (int kk = 0; kk < 4; ++kk)
            #pragma unroll
            for (int np = 0; np < 2; ++np)
                ldsm_x4(bBase + np * 2048 + ((bCol + kk * 32) ^ bXor), B[kk][np]);
    }

    // staging constants: thread covers row mr, u-bytes [ug*16, ug*16+16)
    const int mr = tid >> 3, ug = tid & 7;
    const int mrd = mr / DL, mrm = mr - mrd * DL;
    const uint32_t stOff = (uint32_t)mr * 128 +
                           (((uint32_t)ug * 16) ^ ((uint32_t)(mr & 7) << 4));

    // mainloop A addressing
    const int rA = wm * 16 + (lane & 15);
    const uint32_t aBase = sb + rA * 128;
    const uint32_t aXor = (uint32_t)(rA & 7) << 4;
    const uint32_t aCol = (uint32_t)(lane >> 4) * 16;

    // writer constants
    const int r0 = wm * 16 + (lane >> 2), r1 = r0 + 8;
    const int f0 = (r0 / DL) * SPAN + (r0 % DL);
    const int f1 = (r1 / DL) * SPAN + (r1 % DL);
    const int cb = wq * 32 + (lane & 3) * 2;

    // reader constants
    const int rm = (4 * tid) % SPAN;
    const int nrb = (4 * tid) / SPAN;
    float* const obase = out + ooff + (size_t)h * SPAN;

    // ---- prefetch first tile ----
    uint32_t pf[4];
    {
        const int n = cid * NPT + mrd;
        const float* p = x + (size_t)n * XROW + xoff + mrm;
        #pragma unroll
        for (int k = 0; k < 4; ++k) {
            float v0 = 0.f, v1 = 0.f;
            if (n < Ncap) {
                int u = ug * 8 + 2 * k;
                v0 = p[u * DL];
                v1 = p[u * DL + DL];
            }
            asm("cvt.rn.f16x2.f32 %0, %1, %2;" : "=r"(pf[k]) : "f"(v1), "f"(v0));
        }
    }
    __syncthreads();   // B fragments loaded; W smem region reusable

    for (int mt = cid; mt < ntiles; mt += cstep) {
        const int n0 = mt * NPT;

        // ---- stage A: one STS.128 per thread ----
        *(uint4*)(smem + stOff) = make_uint4(pf[0], pf[1], pf[2], pf[3]);
        __syncthreads();

        // ---- prefetch NEXT tile (overlaps MMA/epilogue) ----
        {
            const int mt2 = mt + cstep;
            const int n = mt2 * NPT + mrd;
            const bool v = (mt2 < ntiles) && (n < Ncap);
            const float* p = x + (size_t)n * XROW + xoff + mrm;
            #pragma unroll
            for (int k = 0; k < 4; ++k) {
                float v0 = 0.f, v1 = 0.f;
                if (v) {
                    int u = ug * 8 + 2 * k;
                    v0 = p[u * DL];
                    v1 = p[u * DL + DL];
                }
                asm("cvt.rn.f16x2.f32 %0, %1, %2;" : "=r"(pf[k]) : "f"(v1), "f"(v0));
            }
        }

        // ---- mainloop: A-ldsm only, B from registers ----
        float acc[4][4];
        #pragma unroll
        for (int nn = 0; nn < 4; ++nn)
            #pragma unroll
            for (int q = 0; q < 4; ++q) acc[nn][q] = 0.f;

        #pragma unroll
        for (int kk = 0; kk < 4; ++kk) {
            uint32_t a[4];
            ldsm_x4(aBase + ((aCol + kk * 32) ^ aXor), a);
            mma_f16(acc[0], a, B[kk][0][0], B[kk][0][1]);
            mma_f16(acc[1], a, B[kk][0][2], B[kk][0][3]);
            mma_f16(acc[2], a, B[kk][1][0], B[kk][1][1]);
            mma_f16(acc[3], a, B[kk][1][2], B[kk][1][3]);
        }

        // ---- writer: output-linear flat Cs, byte-swizzled ----
        #pragma unroll
        for (int nn = 0; nn < 4; ++nn) {
            int c = cb + nn * 8;
            if (DL == 1) {
                uint32_t b0 = (uint32_t)(f0 + c) * 4;
                b0 ^= ((b0 >> 9) & 7u) << 4;
                *(float2*)(smem + CSOFF + b0) = make_float2(acc[nn][0], acc[nn][1]);
                uint32_t b1 = (uint32_t)(f1 + c) * 4;
                b1 ^= ((b1 >> 9) & 7u) << 4;
                *(float2*)(smem + CSOFF + b1) = make_float2(acc[nn][2], acc[nn][3]);
            } else {
                uint32_t b;
                b = (uint32_t)(f0 + c * DL) * 4;        b ^= ((b >> 9) & 7u) << 4;
                *(float*)(smem + CSOFF + b) = acc[nn][0];
                b = (uint32_t)(f0 + (c + 1) * DL) * 4;  b ^= ((b >> 9) & 7u) << 4;
                *(float*)(smem + CSOFF + b) = acc[nn][1];
                b = (uint32_t)(f1 + c * DL) * 4;        b ^= ((b >> 9) & 7u) << 4;
                *(float*)(smem + CSOFF + b) = acc[nn][2];
                b = (uint32_t)(f1 + (c + 1) * DL) * 4;  b ^= ((b >> 9) & 7u) << 4;
                *(float*)(smem + CSOFF + b) = acc[nn][3];
            }
        }
        __syncthreads();

        // ---- reader: flat float4 -> coalesced STG.128 ----
        #pragma unroll
        for (int k = 0; k < 4; ++k) {
            int nr = nrb + k * NRK;
            if (n0 + nr < Ncap) {
                uint32_t b = 16u * (uint32_t)(tid + k * THREADS);
                b ^= ((b >> 9) & 7u) << 4;
                float4 v = *(const float4*)(smem + CSOFF + b);
                *(float4*)(obase + (size_t)(n0 + nr) * OROW + rm) = v;
            }
        }
        // no trailing sync needed: next stage-A writes a disjoint region and
        // the stage-sync orders next writer behind all readers.
    }
}

extern "C" void kernel_launch(void* const* d_in, const int* in_sizes, int n_in,
                              void* d_out, int out_size) {
    const float* x  = (const float*)d_in[0];
    const float* W0 = (const float*)d_in[1];
    const float* W1 = (const float*)d_in[2];
    const float* W2 = (const float*)d_in[3];
    float* out = (float*)d_out;

    const int N = in_sizes[0] / XROW;   // 100000

    constexpr int S1 = 32 * 640;    // 20480
    constexpr int S3 = 48 * 640;    // 30720
    constexpr int S5 = 80 * 640;    // 51200

    cudaFuncSetAttribute(tp5<1, 32, 256>,
                         cudaFuncAttributeMaxDynamicSharedMemorySize, S1);
    cudaFuncSetAttribute(tp5<3, 48, 384>,
                         cudaFuncAttributeMaxDynamicSharedMemorySize, S3);
    cudaFuncSetAttribute(tp5<5, 80, 640>,
                         cudaFuncAttributeMaxDynamicSharedMemorySize, S5);

    prep_w<<<(3 * 64 * 256 + 255) / 256, 256>>>(W0, W1, W2);

    const int T0 = (1 * N + 31) / 32;   // 3125 exact
    const int T1 = (3 * N + 47) / 48;   // 6250 exact
    const int T2 = (5 * N + 79) / 80;   // 6250 exact

    // grid even: half = bid&1; 2 CTAs/SM for 256/384thr, 1 for 640thr
    tp5<1, 32, 256><<<296, 256, S1>>>(x, out, 0,   0,    0, N, T0);
    tp5<3, 48, 384><<<296, 384, S3>>>(x, out, 1,  64,  256, N, T1);
    tp5<5, 80, 640><<<148, 640, S5>>>(x, out, 2, 256, 1024, N, T2);
}

// round 12
// speedup vs baseline: 1.0580x; 1.0580x over previous
#include <cuda_runtime.h>
#include <cuda_fp16.h>
#include <cstdint>

// ---------------------------------------------------------------------------
// E3NN lifting TP: per l, C[M,256] = A[M,64] * W_l[64,256], M = N*(2l+1).
// mma.sync m16n8k16 fp16 (x fp16, W fp16 w/ 1/8 folded), rel_err ~2.9e-4.
// R11: B-in-registers (loaded once per persistent CTA) + 2 CTAs/SM restored:
// CTA covers COLS in {128,64} output cols (HDIV = 256/COLS CTAs per tile),
// sibling CTAs share x reads via L2. Output-linear flat Cs, byte-swizzled:
// conflict-free scatter STS, float4 coalesced LDS->STG. 2 barriers/tile.
// ---------------------------------------------------------------------------

constexpr int XROW = 576;
constexpr int OROW = 2304;

// Pre-transposed fp16 weights (scale 1/8 folded in): [l][w][u]
__device__ __align__(16) __half g_W[3][256][64];

__global__ void prep_w(const float* __restrict__ W0, const float* __restrict__ W1,
                       const float* __restrict__ W2) {
    int idx = blockIdx.x * blockDim.x + threadIdx.x;
    if (idx >= 3 * 64 * 256) return;
    int l = idx / (64 * 256);
    int r = idx - l * (64 * 256);
    int u = r >> 8, w = r & 255;
    const float* W = (l == 0) ? W0 : (l == 1) ? W1 : W2;
    g_W[l][w][u] = __float2half_rn(W[u * 256 + w] * 0.125f);
}

__device__ __forceinline__ uint32_t smem_u32(const void* p) {
    uint32_t a;
    asm("{ .reg .u64 t; cvta.to.shared.u64 t, %1; cvt.u32.u64 %0, t; }" : "=r"(a) : "l"(p));
    return a;
}
__device__ __forceinline__ void ldsm_x4(uint32_t addr, uint32_t* r) {
    asm volatile("ldmatrix.sync.aligned.m8n8.x4.shared.b16 {%0,%1,%2,%3}, [%4];"
                 : "=r"(r[0]), "=r"(r[1]), "=r"(r[2]), "=r"(r[3]) : "r"(addr));
}
__device__ __forceinline__ void mma_f16(float* c, const uint32_t* a,
                                        uint32_t b0, uint32_t b1) {
    asm volatile("mma.sync.aligned.m16n8k16.row.col.f32.f16.f16.f32 "
                 "{%0,%1,%2,%3}, {%4,%5,%6,%7}, {%8,%9}, {%0,%1,%2,%3};"
                 : "+f"(c[0]), "+f"(c[1]), "+f"(c[2]), "+f"(c[3])
                 : "r"(a[0]), "r"(a[1]), "r"(a[2]), "r"(a[3]), "r"(b0), "r"(b1));
}

// MTILE = NPT*DL rows (multiple of 16), COLS output cols per CTA.
// Warps = (MTILE/16) * (COLS/32): wm = wid / NCG (m16 band), wq = wid % NCG.
template <int DL, int NPT, int COLS>
__global__ __launch_bounds__(((NPT * DL) / 16) * (COLS / 32) * 32, (DL == 1 ? 3 : 2))
void tp6(const float* __restrict__ x, float* __restrict__ out,
         int lsel, int xoff, int ooff, int Ncap, int ntiles) {
    constexpr int MTILE = NPT * DL;
    constexpr int NCG = COLS / 32;
    constexpr int THREADS = (MTILE / 16) * NCG * 32;
    constexpr int HDIV = 256 / COLS;
    constexpr int SPAN = COLS * DL;         // out floats per n per CTA
    constexpr int CSOFF = MTILE * 128;      // A region size (bytes)
    constexpr int P = (MTILE * 8) / THREADS;  // staging passes
    constexpr int SR = THREADS / 8;           // rows staged per pass
    constexpr int SP4 = SPAN / 4;             // float4 per n

    extern __shared__ char smem[];
    const uint32_t sb = smem_u32(smem);
    const int tid = threadIdx.x, lane = tid & 31, wid = tid >> 5;
    const int wm = wid / NCG, wq = wid % NCG;
    const int h = (int)(blockIdx.x % HDIV);
    const int cid = (int)(blockIdx.x / HDIV);
    const int cstep = (int)(gridDim.x / HDIV);

    // ---- stage this CTA's W slice (COLS rows x 64 u) into SW128 smem ----
    {
        const uint4* wsrc = (const uint4*)&g_W[lsel][h * COLS][0];
        for (int t = tid; t < COLS * 8; t += THREADS) {
            int w = t >> 3;
            uint32_t c = (uint32_t)(t & 7) * 16;
            *(uint4*)(smem + w * 128 + (c ^ ((w & 7) << 4))) = wsrc[t];
        }
    }
    __syncthreads();

    // ---- load B fragments ONCE into registers ----
    uint32_t B[4][2][4];   // [kk][16-row pair][4 regs] = 32 regs
    {
        const int bRow = (lane & 7) + ((lane >> 4) << 3);
        const uint32_t bXor = (uint32_t)(bRow & 7) << 4;
        const uint32_t bCol = (uint32_t)((lane >> 3) & 1) * 16;
        const uint32_t bBase = sb + (uint32_t)(wq * 32 + bRow) * 128;
        #pragma unroll
        for (int kk = 0; kk < 4; ++kk)
            #pragma unroll
            for (int np = 0; np < 2; ++np)
                ldsm_x4(bBase + np * 2048 + ((bCol + kk * 32) ^ bXor), B[kk][np]);
    }

    // staging constants
    const int ug = tid & 7;
    int mrdA[P], mrmA[P];
    uint32_t stO[P];
    #pragma unroll
    for (int p = 0; p < P; ++p) {
        int mr = (tid >> 3) + p * SR;
        mrdA[p] = mr / DL;
        mrmA[p] = mr - mrdA[p] * DL;
        stO[p] = (uint32_t)mr * 128 +
                 (((uint32_t)ug * 16) ^ ((uint32_t)(mr & 7) << 4));
    }

    // mainloop A addressing
    const int rA = wm * 16 + (lane & 15);
    const uint32_t aBase = sb + rA * 128;
    const uint32_t aXor = (uint32_t)(rA & 7) << 4;
    const uint32_t aCol = (uint32_t)(lane >> 4) * 16;

    // writer constants
    const int r0 = wm * 16 + (lane >> 2), r1 = r0 + 8;
    const int f0 = (r0 / DL) * SPAN + (r0 % DL);
    const int f1 = (r1 / DL) * SPAN + (r1 % DL);
    const int cb = wq * 32 + (lane & 3) * 2;

    float* const obase = out + ooff + (size_t)h * SPAN;

    // ---- prefetch first tile ----
    uint32_t pf[4 * P];
    {
        const int nb = cid * NPT;
        #pragma unroll
        for (int p = 0; p < P; ++p) {
            const int n = nb + mrdA[p];
            const float* ptr = x + (size_t)n * XROW + xoff + mrmA[p];
            #pragma unroll
            for (int k = 0; k < 4; ++k) {
                float v0 = 0.f, v1 = 0.f;
                if (n < Ncap) {
                    int u = ug * 8 + 2 * k;
                    v0 = ptr[u * DL];
                    v1 = ptr[u * DL + DL];
                }
                asm("cvt.rn.f16x2.f32 %0, %1, %2;"
                    : "=r"(pf[p * 4 + k]) : "f"(v1), "f"(v0));
            }
        }
    }
    __syncthreads();   // B loaded; W smem region reusable for A/Cs

    for (int mt = cid; mt < ntiles; mt += cstep) {
        const int n0 = mt * NPT;

        // ---- stage A: one STS.128 per thread per pass ----
        #pragma unroll
        for (int p = 0; p < P; ++p)
            *(uint4*)(smem + stO[p]) =
                make_uint4(pf[p * 4], pf[p * 4 + 1], pf[p * 4 + 2], pf[p * 4 + 3]);
        __syncthreads();

        // ---- prefetch NEXT tile (overlaps MMA/epilogue) ----
        {
            const int mt2 = mt + cstep;
            const bool vt = mt2 < ntiles;
            const int nb2 = mt2 * NPT;
            #pragma unroll
            for (int p = 0; p < P; ++p) {
                const int n = nb2 + mrdA[p];
                const float* ptr = x + (size_t)n * XROW + xoff + mrmA[p];
                #pragma unroll
                for (int k = 0; k < 4; ++k) {
                    float v0 = 0.f, v1 = 0.f;
                    if (vt && n < Ncap) {
                        int u = ug * 8 + 2 * k;
                        v0 = ptr[u * DL];
                        v1 = ptr[u * DL + DL];
                    }
                    asm("cvt.rn.f16x2.f32 %0, %1, %2;"
                        : "=r"(pf[p * 4 + k]) : "f"(v1), "f"(v0));
                }
            }
        }

        // ---- mainloop: A-ldsm only, B from registers ----
        float acc[4][4];
        #pragma unroll
        for (int nn = 0; nn < 4; ++nn)
            #pragma unroll
            for (int q = 0; q < 4; ++q) acc[nn][q] = 0.f;

        #pragma unroll
        for (int kk = 0; kk < 4; ++kk) {
            uint32_t a[4];
            ldsm_x4(aBase + ((aCol + kk * 32) ^ aXor), a);
            mma_f16(acc[0], a, B[kk][0][0], B[kk][0][1]);
            mma_f16(acc[1], a, B[kk][0][2], B[kk][0][3]);
            mma_f16(acc[2], a, B[kk][1][0], B[kk][1][1]);
            mma_f16(acc[3], a, B[kk][1][2], B[kk][1][3]);
        }

        // ---- writer: output-linear flat Cs, byte-swizzled ----
        #pragma unroll
        for (int nn = 0; nn < 4; ++nn) {
            int c = cb + nn * 8;
            if (DL == 1) {
                uint32_t b0 = (uint32_t)(f0 + c) * 4;
                b0 ^= ((b0 >> 9) & 7u) << 4;
                *(float2*)(smem + CSOFF + b0) = make_float2(acc[nn][0], acc[nn][1]);
                uint32_t b1 = (uint32_t)(f1 + c) * 4;
                b1 ^= ((b1 >> 9) & 7u) << 4;
                *(float2*)(smem + CSOFF + b1) = make_float2(acc[nn][2], acc[nn][3]);
            } else {
                uint32_t b;
                b = (uint32_t)(f0 + c * DL) * 4;        b ^= ((b >> 9) & 7u) << 4;
                *(float*)(smem + CSOFF + b) = acc[nn][0];
                b = (uint32_t)(f0 + (c + 1) * DL) * 4;  b ^= ((b >> 9) & 7u) << 4;
                *(float*)(smem + CSOFF + b) = acc[nn][1];
                b = (uint32_t)(f1 + c * DL) * 4;        b ^= ((b >> 9) & 7u) << 4;
                *(float*)(smem + CSOFF + b) = acc[nn][2];
                b = (uint32_t)(f1 + (c + 1) * DL) * 4;  b ^= ((b >> 9) & 7u) << 4;
                *(float*)(smem + CSOFF + b) = acc[nn][3];
            }
        }
        __syncthreads();

        // ---- reader: flat float4 -> coalesced STG.128 (4 exact passes) ----
        #pragma unroll
        for (int k = 0; k < 4; ++k) {
            int q = tid + k * THREADS;
            int nr = q / SP4;
            int rm4 = q - nr * SP4;
            if (n0 + nr < Ncap) {
                uint32_t b = 16u * (uint32_t)q;
                b ^= ((b >> 9) & 7u) << 4;
                float4 v = *(const float4*)(smem + CSOFF + b);
                *(float4*)(obase + (size_t)(n0 + nr) * OROW + rm4 * 4) = v;
            }
        }
        // next stage-A writes a disjoint region; its barrier orders Cs reuse.
    }
}

extern "C" void kernel_launch(void* const* d_in, const int* in_sizes, int n_in,
                              void* d_out, int out_size) {
    const float* x  = (const float*)d_in[0];
    const float* W0 = (const float*)d_in[1];
    const float* W1 = (const float*)d_in[2];
    const float* W2 = (const float*)d_in[3];
    float* out = (float*)d_out;

    const int N = in_sizes[0] / XROW;   // 100000

    // smem = A (MTILE*128B) + Cs (MTILE*COLS*4B); W slice (COLS*128B) aliases
    constexpr int S1 = 32 * 128 + 32 * 128 * 4;   // 20480
    constexpr int S3 = 48 * 128 + 48 * 128 * 4;   // 30720
    constexpr int S5 = 80 * 128 + 80 * 64 * 4;    // 30720

    cudaFuncSetAttribute(tp6<1, 32, 128>,
                         cudaFuncAttributeMaxDynamicSharedMemorySize, S1);
    cudaFuncSetAttribute(tp6<3, 16, 128>,
                         cudaFuncAttributeMaxDynamicSharedMemorySize, S3);
    cudaFuncSetAttribute(tp6<5, 16, 64>,
                         cudaFuncAttributeMaxDynamicSharedMemorySize, S5);

    prep_w<<<(3 * 64 * 256 + 255) / 256, 256>>>(W0, W1, W2);

    const int T0 = (N + 31) / 32;   // 3125 exact
    const int T1 = (N + 15) / 16;   // 6250 exact
    const int T2 = (N + 15) / 16;   // 6250 exact

    // grids divisible by HDIV (2, 2, 4)
    tp6<1, 32, 128><<<296, 256, S1>>>(x, out, 0,   0,    0, N, T0);
    tp6<3, 16, 128><<<296, 384, S3>>>(x, out, 1,  64,  256, N, T1);
    tp6<5, 16, 64><<<296, 320, S5>>>(x, out, 2, 256, 1024, N, T2);
}

// round 13
// speedup vs baseline: 1.0600x; 1.0019x over previous
#include <cuda_runtime.h>
#include <cuda_fp16.h>
#include <cstdint>

// ---------------------------------------------------------------------------
// E3NN lifting TP, R12: pre-transposed fp16 A in GMEM.
//   pre kernels: x (fp32, u-strided) -> g_A[l][m][u] fp16, SW128 swizzle
//   pre-applied. Main kernels: cp.async double-buffered flat A copy,
//   B-in-registers mainloop, output-linear swizzled Cs epilogue.
// rel_err ~2.9e-4 (x fp16 + W fp16 with 1/8 folded).
// ---------------------------------------------------------------------------

constexpr int XROW = 576;
constexpr int OROW = 2304;

constexpr int M0P = 100032;   // 1563 * 64
constexpr int M1P = 300000;   // 3125 * 96
constexpr int M2P = 500000;   // 3125 * 160

__device__ __align__(16) __half g_A0[(size_t)M0P * 64];
__device__ __align__(16) __half g_A1[(size_t)M1P * 64];
__device__ __align__(16) __half g_A2[(size_t)M2P * 64];
__device__ __align__(16) __half g_W[3][256][64];

__global__ void prep_w(const float* __restrict__ W0, const float* __restrict__ W1,
                       const float* __restrict__ W2) {
    int idx = blockIdx.x * blockDim.x + threadIdx.x;
    if (idx >= 3 * 64 * 256) return;
    int l = idx / (64 * 256);
    int r = idx - l * (64 * 256);
    int u = r >> 8, w = r & 255;
    const float* W = (l == 0) ? W0 : (l == 1) ? W1 : W2;
    g_W[l][w][u] = __float2half_rn(W[u * 256 + w] * 0.125f);
}

// ---- pre: DL=1 (no transpose, coalesced convert) ----
__global__ void pre1(const float* __restrict__ x) {
    int m = blockIdx.x * 64 + (threadIdx.x >> 2);
    int seg = threadIdx.x & 3;               // 16 floats per seg
    if (m >= 100000) return;
    const float4* p = (const float4*)(x + (size_t)m * XROW) + seg * 4;
    uint32_t h[8];
    #pragma unroll
    for (int j = 0; j < 4; ++j) {
        float4 v = p[j];
        asm("cvt.rn.f16x2.f32 %0, %1, %2;" : "=r"(h[2*j])   : "f"(v.y), "f"(v.x));
        asm("cvt.rn.f16x2.f32 %0, %1, %2;" : "=r"(h[2*j+1]) : "f"(v.w), "f"(v.z));
    }
    char* dst = (char*)g_A0 + (size_t)m * 128;
    uint32_t c0 = (uint32_t)(seg * 32)      ^ ((uint32_t)(m & 7) << 4);
    uint32_t c1 = (uint32_t)(seg * 32 + 16) ^ ((uint32_t)(m & 7) << 4);
    *(uint4*)(dst + c0) = make_uint4(h[0], h[1], h[2], h[3]);
    *(uint4*)(dst + c1) = make_uint4(h[4], h[5], h[6], h[7]);
}

// ---- pre: DL in {3,5} (strided gather + convert, once) ----
template <int DL>
__global__ void preT(const float* __restrict__ x, __half* __restrict__ gA,
                     int xoff, int Mtot) {
    int m = blockIdx.x * 32 + (threadIdx.x >> 3);
    int ug = threadIdx.x & 7;
    if (m >= Mtot) return;
    int n = m / DL, i = m - n * DL;
    const float* p = x + (size_t)n * XROW + xoff + i;
    uint32_t h[4];
    #pragma unroll
    for (int k = 0; k < 4; ++k) {
        int u = ug * 8 + 2 * k;
        float v0 = p[u * DL];
        float v1 = p[u * DL + DL];
        asm("cvt.rn.f16x2.f32 %0, %1, %2;" : "=r"(h[k]) : "f"(v1), "f"(v0));
    }
    char* dst = (char*)gA + (size_t)m * 128;
    uint32_t c = (uint32_t)(ug * 16) ^ ((uint32_t)(m & 7) << 4);
    *(uint4*)(dst + c) = make_uint4(h[0], h[1], h[2], h[3]);
}

__device__ __forceinline__ uint32_t smem_u32(const void* p) {
    uint32_t a;
    asm("{ .reg .u64 t; cvta.to.shared.u64 t, %1; cvt.u32.u64 %0, t; }" : "=r"(a) : "l"(p));
    return a;
}
__device__ __forceinline__ void ldsm_x4(uint32_t addr, uint32_t* r) {
    asm volatile("ldmatrix.sync.aligned.m8n8.x4.shared.b16 {%0,%1,%2,%3}, [%4];"
                 : "=r"(r[0]), "=r"(r[1]), "=r"(r[2]), "=r"(r[3]) : "r"(addr));
}
__device__ __forceinline__ void mma_f16(float* c, const uint32_t* a,
                                        uint32_t b0, uint32_t b1) {
    asm volatile("mma.sync.aligned.m16n8k16.row.col.f32.f16.f16.f32 "
                 "{%0,%1,%2,%3}, {%4,%5,%6,%7}, {%8,%9}, {%0,%1,%2,%3};"
                 : "+f"(c[0]), "+f"(c[1]), "+f"(c[2]), "+f"(c[3])
                 : "r"(a[0]), "r"(a[1]), "r"(a[2]), "r"(a[3]), "r"(b0), "r"(b1));
}
__device__ __forceinline__ void cpa16(uint32_t s, const void* g) {
    asm volatile("cp.async.cg.shared.global [%0], [%1], 16;" :: "r"(s), "l"(g));
}

// MTILE = NPT*DL (multiple of 32). Warps = (MTILE/32) * (COLS/32).
// wm = wid / NCG covers rows [wm*32, wm*32+32) (2 m16 bands); wq = wid % NCG.
template <int DL, int NPT, int COLS, int OCC>
__global__ __launch_bounds__((((NPT * DL) / 32) * (COLS / 32)) * 32, OCC)
void tp8(const __half* __restrict__ gA, float* __restrict__ out,
         int lsel, int ooff, int Ncap, int ntiles) {
    constexpr int MTILE = NPT * DL;
    constexpr int NCG = COLS / 32;
    constexpr int THREADS = ((MTILE / 32) * NCG) * 32;
    constexpr int HDIV = 256 / COLS;
    constexpr int SPAN = COLS * DL;
    constexpr int SP4 = SPAN / 4;
    constexpr int ABYTES = MTILE * 128;
    constexpr int CSOFF = 2 * ABYTES;          // double-buffered A, then Cs
    constexpr int PCH = (MTILE * 8) / THREADS; // 16B chunks per thread
    constexpr int RP = (MTILE * COLS) / (4 * THREADS);  // reader float4/thread

    extern __shared__ char smem[];
    const uint32_t sb = smem_u32(smem);
    const int tid = threadIdx.x, lane = tid & 31, wid = tid >> 5;
    const int wm = wid / NCG, wq = wid % NCG;
    const int h = (int)(blockIdx.x % HDIV);
    const int cid = (int)(blockIdx.x / HDIV);
    const int cstep = (int)(gridDim.x / HDIV);

    // ---- prologue: start cp.async for first tile into buffer 0 ----
    {
        const char* g = (const char*)gA + (size_t)cid * MTILE * 128;
        #pragma unroll
        for (int p = 0; p < PCH; ++p) {
            int q = tid + p * THREADS;
            cpa16(sb + q * 16, g + q * 16);
        }
        asm volatile("cp.async.commit_group;" ::: "memory");
    }

    // ---- stage W slice into Cs region (SW128), then B frags to regs ----
    {
        const uint4* wsrc = (const uint4*)&g_W[lsel][h * COLS][0];
        for (int t = tid; t < COLS * 8; t += THREADS) {
            int w = t >> 3;
            uint32_t c = (uint32_t)(t & 7) * 16;
            *(uint4*)(smem + CSOFF + w * 128 + (c ^ ((w & 7) << 4))) = wsrc[t];
        }
    }
    __syncthreads();

    uint32_t B[4][2][4];
    {
        const int bRow = (lane & 7) + ((lane >> 4) << 3);
        const uint32_t bXor = (uint32_t)(bRow & 7) << 4;
        const uint32_t bCol = (uint32_t)((lane >> 3) & 1) * 16;
        const uint32_t bBase = sb + CSOFF + (uint32_t)(wq * 32 + bRow) * 128;
        #pragma unroll
        for (int kk = 0; kk < 4; ++kk)
            #pragma unroll
            for (int np = 0; np < 2; ++np)
                ldsm_x4(bBase + np * 2048 + ((bCol + kk * 32) ^ bXor), B[kk][np]);
    }

    // mainloop A addressing (per band)
    const int rA0 = wm * 32 + (lane & 15);
    const uint32_t aXor0 = (uint32_t)(rA0 & 7) << 4;
    const uint32_t aCol = (uint32_t)(lane >> 4) * 16;

    // writer constants per band
    int fr[2][2];  // [band][r0/r1]
    #pragma unroll
    for (int b = 0; b < 2; ++b) {
        int r0 = wm * 32 + b * 16 + (lane >> 2);
        int r1 = r0 + 8;
        fr[b][0] = (r0 / DL) * SPAN + (r0 % DL);
        fr[b][1] = (r1 / DL) * SPAN + (r1 % DL);
    }
    const int cb = wq * 32 + (lane & 3) * 2;

    float* const obase = out + ooff + (size_t)h * SPAN;

    int buf = 0;
    for (int mt = cid; mt < ntiles; mt += cstep) {
        const int n0 = mt * NPT;

        asm volatile("cp.async.wait_group 0;" ::: "memory");
        __syncthreads();   // A[buf] ready; prev reader done

        // ---- start next tile's copy into the other buffer ----
        {
            const int mt2 = mt + cstep;
            if (mt2 < ntiles) {
                const char* g = (const char*)gA + (size_t)mt2 * MTILE * 128;
                const uint32_t so = sb + (buf ^ 1) * ABYTES;
                #pragma unroll
                for (int p = 0; p < PCH; ++p) {
                    int q = tid + p * THREADS;
                    cpa16(so + q * 16, g + q * 16);
                }
            }
            asm volatile("cp.async.commit_group;" ::: "memory");
        }

        // ---- mainloop: A-ldsm (2 bands), B from registers ----
        float acc[2][4][4];
        #pragma unroll
        for (int b = 0; b < 2; ++b)
            #pragma unroll
            for (int nn = 0; nn < 4; ++nn)
                #pragma unroll
                for (int q = 0; q < 4; ++q) acc[b][nn][q] = 0.f;

        const uint32_t aB = sb + buf * ABYTES + (uint32_t)rA0 * 128;
        #pragma unroll
        for (int kk = 0; kk < 4; ++kk) {
            const uint32_t ac = (aCol + kk * 32) ^ aXor0;
            uint32_t a0[4], a1[4];
            ldsm_x4(aB + ac, a0);
            ldsm_x4(aB + 16 * 128 + ac, a1);
            mma_f16(acc[0][0], a0, B[kk][0][0], B[kk][0][1]);
            mma_f16(acc[0][1], a0, B[kk][0][2], B[kk][0][3]);
            mma_f16(acc[0][2], a0, B[kk][1][0], B[kk][1][1]);
            mma_f16(acc[0][3], a0, B[kk][1][2], B[kk][1][3]);
            mma_f16(acc[1][0], a1, B[kk][0][0], B[kk][0][1]);
            mma_f16(acc[1][1], a1, B[kk][0][2], B[kk][0][3]);
            mma_f16(acc[1][2], a1, B[kk][1][0], B[kk][1][1]);
            mma_f16(acc[1][3], a1, B[kk][1][2], B[kk][1][3]);
        }

        // ---- writer: output-linear flat Cs, byte-swizzled ----
        #pragma unroll
        for (int b = 0; b < 2; ++b)
            #pragma unroll
            for (int nn = 0; nn < 4; ++nn) {
                int c = cb + nn * 8;
                if (DL == 1) {
                    uint32_t b0 = (uint32_t)(fr[b][0] + c) * 4;
                    b0 ^= ((b0 >> 9) & 7u) << 4;
                    *(float2*)(smem + CSOFF + b0) =
                        make_float2(acc[b][nn][0], acc[b][nn][1]);
                    uint32_t b1 = (uint32_t)(fr[b][1] + c) * 4;
                    b1 ^= ((b1 >> 9) & 7u) << 4;
                    *(float2*)(smem + CSOFF + b1) =
                        make_float2(acc[b][nn][2], acc[b][nn][3]);
                } else {
                    uint32_t a;
                    a = (uint32_t)(fr[b][0] + c * DL) * 4;       a ^= ((a >> 9) & 7u) << 4;
                    *(float*)(smem + CSOFF + a) = acc[b][nn][0];
                    a = (uint32_t)(fr[b][0] + (c + 1) * DL) * 4; a ^= ((a >> 9) & 7u) << 4;
                    *(float*)(smem + CSOFF + a) = acc[b][nn][1];
                    a = (uint32_t)(fr[b][1] + c * DL) * 4;       a ^= ((a >> 9) & 7u) << 4;
                    *(float*)(smem + CSOFF + a) = acc[b][nn][2];
                    a = (uint32_t)(fr[b][1] + (c + 1) * DL) * 4; a ^= ((a >> 9) & 7u) << 4;
                    *(float*)(smem + CSOFF + a) = acc[b][nn][3];
                }
            }
        __syncthreads();

        // ---- reader: flat float4 -> coalesced STG.128 ----
        #pragma unroll
        for (int k = 0; k < RP; ++k) {
            int q = tid + k * THREADS;
            int nr = q / SP4;
            int rm4 = q - nr * SP4;
            if (n0 + nr < Ncap) {
                uint32_t a = 16u * (uint32_t)q;
                a ^= ((a >> 9) & 7u) << 4;
                float4 v = *(const float4*)(smem + CSOFF + a);
                *(float4*)(obase + (size_t)(n0 + nr) * OROW + rm4 * 4) = v;
            }
        }
        buf ^= 1;
    }
}

extern "C" void kernel_launch(void* const* d_in, const int* in_sizes, int n_in,
                              void* d_out, int out_size) {
    const float* x  = (const float*)d_in[0];
    const float* W0 = (const float*)d_in[1];
    const float* W1 = (const float*)d_in[2];
    const float* W2 = (const float*)d_in[3];
    float* out = (float*)d_out;

    const int N = in_sizes[0] / XROW;   // 100000

    // smem = 2*A + Cs
    constexpr int S1 = 2 * 64 * 128 + 64 * 128 * 4;    // 49152
    constexpr int S3 = 2 * 96 * 128 + 96 * 64 * 4;     // 49152
    constexpr int S5 = 2 * 160 * 128 + 160 * 64 * 4;   // 81920

    cudaFuncSetAttribute(tp8<1, 64, 128, 2>,
                         cudaFuncAttributeMaxDynamicSharedMemorySize, S1);
    cudaFuncSetAttribute(tp8<3, 32, 64, 3>,
                         cudaFuncAttributeMaxDynamicSharedMemorySize, S3);
    cudaFuncSetAttribute(tp8<5, 32, 64, 2>,
                         cudaFuncAttributeMaxDynamicSharedMemorySize, S5);

    prep_w<<<(3 * 64 * 256 + 255) / 256, 256>>>(W0, W1, W2);

    __half* a0p = nullptr; cudaGetSymbolAddress((void**)&a0p, g_A0);
    __half* a1p = nullptr; cudaGetSymbolAddress((void**)&a1p, g_A1);
    __half* a2p = nullptr; cudaGetSymbolAddress((void**)&a2p, g_A2);

    pre1<<<(100000 + 63) / 64, 256>>>(x);
    preT<3><<<(3 * N + 31) / 32, 256>>>(x, a1p,  64, 3 * N);
    preT<5><<<(5 * N + 31) / 32, 256>>>(x, a2p, 256, 5 * N);

    const int T0 = (N + 63) / 64;   // 1563 (last partial, guarded)
    const int T1 = (N + 31) / 32;   // 3125 exact
    const int T2 = (N + 31) / 32;   // 3125 exact

    // grids divisible by HDIV (2, 4, 4)
    tp8<1, 64, 128, 2><<<296, 256, S1>>>(a0p, out, 0,    0, N, T0);
    tp8<3, 32, 64, 3><<<296, 192, S3>>>(a1p, out, 1,  256, N, T1);
    tp8<5, 32, 64, 2><<<296, 320, S5>>>(a2p, out, 2, 1024, N, T2);
}

// round 15
// speedup vs baseline: 1.0928x; 1.0310x over previous
#include <cuda_runtime.h>
#include <cuda_fp16.h>
#include <cstdint>

// ---------------------------------------------------------------------------
// E3NN lifting TP, R13: ONE fused pre kernel (x -> fp16 A arrays for all l +
// W prep), then 3 mma.sync mains (cp.async double-buffered A, B-in-regs).
// DL=1 main stores fragments directly (no Cs). rel_err ~2.9e-4.
// Launch order [pre, tp5, tp3, tp1] so ncu (-s 5 -c 1) captures tp5.
// ---------------------------------------------------------------------------

constexpr int XROW = 576;
constexpr int OROW = 2304;

constexpr int M0P = 100032;   // 1563 * 64
constexpr int M1P = 300000;   // 3125 * 96
constexpr int M2P = 500000;   // 3125 * 160

__device__ __align__(16) __half g_A0[(size_t)M0P * 64];
__device__ __align__(16) __half g_A1[(size_t)M1P * 64];
__device__ __align__(16) __half g_A2[(size_t)M2P * 64];
__device__ __align__(16) __half g_W[3][256][64];

// ---- fused pre: 6250 CTAs transpose x (16 n-rows each); 64 CTAs do W ----
__global__ __launch_bounds__(256)
void pre_all(const float* __restrict__ x, const float* __restrict__ W0,
             const float* __restrict__ W1, const float* __restrict__ W2) {
    const int tid = threadIdx.x;
    if (blockIdx.x >= 6250) {
        int base = (int)(blockIdx.x - 6250) * 256 + tid;
        #pragma unroll
        for (int j = 0; j < 3; ++j) {
            int idx = base + j * 16384;          // < 49152
            int l = idx >> 14;
            int r = idx & 16383;
            int u = r >> 8, w = r & 255;
            const float* W = (l == 0) ? W0 : (l == 1) ? W1 : W2;
            g_W[l][w][u] = __float2half_rn(W[u * 256 + w] * 0.125f);
        }
        return;
    }
    __shared__ float sx[16 * 580];               // 580-word row stride (pad)
    const int nb = (int)blockIdx.x * 16;
    {
        const float4* xp = (const float4*)(x + (size_t)nb * XROW);
        #pragma unroll
        for (int j = 0; j < 9; ++j) {
            int idx = tid + j * 256;             // < 2304
            int row = idx / 144, c4 = idx - row * 144;
            float4 v = xp[(size_t)row * 144 + c4];
            *(float4*)&sx[row * 580 + c4 * 4] = v;
        }
    }
    __syncthreads();
    // 144 dest m-rows (l0:16, l1:48, l2:80) x 8 u-groups = 1152 tasks
    for (int q = tid; q < 1152; q += 256) {
        int ug = q & 7, dr = q >> 3;
        int DL, xoff, mloc;
        char* gA;
        size_t mg;
        if (dr < 16)      { DL = 1; xoff = 0;   mloc = dr;      gA = (char*)g_A0; mg = (size_t)nb + mloc; }
        else if (dr < 64) { DL = 3; xoff = 64;  mloc = dr - 16; gA = (char*)g_A1; mg = (size_t)nb * 3 + mloc; }
        else              { DL = 5; xoff = 256; mloc = dr - 64; gA = (char*)g_A2; mg = (size_t)nb * 5 + mloc; }
        int nl = mloc / DL, i = mloc - nl * DL;
        const float* p = &sx[nl * 580 + xoff + i];
        uint32_t h[4];
        #pragma unroll
        for (int k = 0; k < 4; ++k) {
            int u = ug * 8 + 2 * k;
            float v0 = p[u * DL];
            float v1 = p[u * DL + DL];
            asm("cvt.rn.f16x2.f32 %0, %1, %2;" : "=r"(h[k]) : "f"(v1), "f"(v0));
        }
        uint32_t c = (uint32_t)(ug * 16) ^ ((uint32_t)(mg & 7) << 4);
        *(uint4*)(gA + mg * 128 + c) = make_uint4(h[0], h[1], h[2], h[3]);
    }
}

__device__ __forceinline__ uint32_t smem_u32(const void* p) {
    uint32_t a;
    asm("{ .reg .u64 t; cvta.to.shared.u64 t, %1; cvt.u32.u64 %0, t; }" : "=r"(a) : "l"(p));
    return a;
}
__device__ __forceinline__ void ldsm_x4(uint32_t addr, uint32_t* r) {
    asm volatile("ldmatrix.sync.aligned.m8n8.x4.shared.b16 {%0,%1,%2,%3}, [%4];"
                 : "=r"(r[0]), "=r"(r[1]), "=r"(r[2]), "=r"(r[3]) : "r"(addr));
}
__device__ __forceinline__ void mma_f16(float* c, const uint32_t* a,
                                        uint32_t b0, uint32_t b1) {
    asm volatile("mma.sync.aligned.m16n8k16.row.col.f32.f16.f16.f32 "
                 "{%0,%1,%2,%3}, {%4,%5,%6,%7}, {%8,%9}, {%0,%1,%2,%3};"
                 : "+f"(c[0]), "+f"(c[1]), "+f"(c[2]), "+f"(c[3])
                 : "r"(a[0]), "r"(a[1]), "r"(a[2]), "r"(a[3]), "r"(b0), "r"(b1));
}
__device__ __forceinline__ void cpa16(uint32_t s, const void* g) {
    asm volatile("cp.async.cg.shared.global [%0], [%1], 16;" :: "r"(s), "l"(g));
}

// MTILE = NPT*DL (mult of 32). Warps = (MTILE/32)*(COLS/32); warp covers
// 32 rows (2 m16 bands) x 32 cols. DL==1: direct fragment STG (no Cs).
template <int DL, int NPT, int COLS, int OCC>
__global__ __launch_bounds__((((NPT * DL) / 32) * (COLS / 32)) * 32, OCC)
void tp9(const __half* __restrict__ gA, float* __restrict__ out,
         int ooff, int Ncap, int ntiles) {
    constexpr int MTILE = NPT * DL;
    constexpr int NCG = COLS / 32;
    constexpr int THREADS = ((MTILE / 32) * NCG) * 32;
    constexpr int HDIV = 256 / COLS;
    constexpr int SPAN = COLS * DL;
    constexpr int SP4 = SPAN / 4;
    constexpr int ABYTES = MTILE * 128;
    constexpr int CSOFF = 2 * ABYTES;
    constexpr int WOFF = (DL == 1) ? 0 : CSOFF;   // W-staging region
    constexpr int PCH = (MTILE * 8) / THREADS;
    constexpr int RP = (MTILE * COLS) / (4 * THREADS);

    extern __shared__ char smem[];
    const uint32_t sb = smem_u32(smem);
    const int tid = threadIdx.x, lane = tid & 31, wid = tid >> 5;
    const int wm = wid / NCG, wq = wid % NCG;
    const int h = (int)(blockIdx.x % HDIV);
    const int cid = (int)(blockIdx.x / HDIV);
    const int cstep = (int)(gridDim.x / HDIV);

    // ---- stage W slice (COLS x 64) SW128 ----
    {
        const uint4* wsrc = (const uint4*)&g_W[0][0][0] +
                            ((size_t)( (DL==1?0:(DL==3?1:2)) * 256 + h * COLS) * 8);
        for (int t = tid; t < COLS * 8; t += THREADS) {
            int w = t >> 3;
            uint32_t c = (uint32_t)(t & 7) * 16;
            *(uint4*)(smem + WOFF + w * 128 + (c ^ ((w & 7) << 4))) = wsrc[t];
        }
    }
    __syncthreads();

    // ---- B fragments once into registers ----
    uint32_t B[4][2][4];
    {
        const int bRow = (lane & 7) + ((lane >> 4) << 3);
        const uint32_t bXor = (uint32_t)(bRow & 7) << 4;
        const uint32_t bCol = (uint32_t)((lane >> 3) & 1) * 16;
        const uint32_t bBase = sb + WOFF + (uint32_t)(wq * 32 + bRow) * 128;
        #pragma unroll
        for (int kk = 0; kk < 4; ++kk)
            #pragma unroll
            for (int np = 0; np < 2; ++np)
                ldsm_x4(bBase + np * 2048 + ((bCol + kk * 32) ^ bXor), B[kk][np]);
    }
    __syncthreads();   // all B loads done before cp.async may overwrite (DL==1)

    // ---- prologue: first tile into buffer 0 ----
    {
        const char* g = (const char*)gA + (size_t)cid * MTILE * 128;
        #pragma unroll
        for (int p = 0; p < PCH; ++p) {
            int q = tid + p * THREADS;
            cpa16(sb + q * 16, g + q * 16);
        }
        asm volatile("cp.async.commit_group;" ::: "memory");
    }

    const int rA0 = wm * 32 + (lane & 15);
    const uint32_t aXor0 = (uint32_t)(rA0 & 7) << 4;
    const uint32_t aCol = (uint32_t)(lane >> 4) * 16;

    int fr[2][2];
    #pragma unroll
    for (int b = 0; b < 2; ++b) {
        int r0 = wm * 32 + b * 16 + (lane >> 2);
        int r1 = r0 + 8;
        fr[b][0] = (r0 / DL) * SPAN + (r0 % DL);
        fr[b][1] = (r1 / DL) * SPAN + (r1 % DL);
    }
    const int cb = wq * 32 + (lane & 3) * 2;
    const int rloc0 = wm * 32 + (lane >> 2);   // DL==1 direct path

    float* const obase = out + ooff + (size_t)h * SPAN;

    int buf = 0;
    for (int mt = cid; mt < ntiles; mt += cstep) {
        const int n0 = mt * NPT;

        asm volatile("cp.async.wait_group 0;" ::: "memory");
        __syncthreads();

        {
            const int mt2 = mt + cstep;
            if (mt2 < ntiles) {
                const char* g = (const char*)gA + (size_t)mt2 * MTILE * 128;
                const uint32_t so = sb + (buf ^ 1) * ABYTES;
                #pragma unroll
                for (int p = 0; p < PCH; ++p) {
                    int q = tid + p * THREADS;
                    cpa16(so + q * 16, g + q * 16);
                }
            }
            asm volatile("cp.async.commit_group;" ::: "memory");
        }

        float acc[2][4][4];
        #pragma unroll
        for (int b = 0; b < 2; ++b)
            #pragma unroll
            for (int nn = 0; nn < 4; ++nn)
                #pragma unroll
                for (int q = 0; q < 4; ++q) acc[b][nn][q] = 0.f;

        const uint32_t aB = sb + buf * ABYTES + (uint32_t)rA0 * 128;
        #pragma unroll
        for (int kk = 0; kk < 4; ++kk) {
            const uint32_t ac = (aCol + kk * 32) ^ aXor0;
            uint32_t a0[4], a1[4];
            ldsm_x4(aB + ac, a0);
            ldsm_x4(aB + 16 * 128 + ac, a1);
            mma_f16(acc[0][0], a0, B[kk][0][0], B[kk][0][1]);
            mma_f16(acc[0][1], a0, B[kk][0][2], B[kk][0][3]);
            mma_f16(acc[0][2], a0, B[kk][1][0], B[kk][1][1]);
            mma_f16(acc[0][3], a0, B[kk][1][2], B[kk][1][3]);
            mma_f16(acc[1][0], a1, B[kk][0][0], B[kk][0][1]);
            mma_f16(acc[1][1], a1, B[kk][0][2], B[kk][0][3]);
            mma_f16(acc[1][2], a1, B[kk][1][0], B[kk][1][1]);
            mma_f16(acc[1][3], a1, B[kk][1][2], B[kk][1][3]);
        }

        if (DL == 1) {
            // direct fragment stores: cols are output-contiguous for d=1
            #pragma unroll
            for (int b = 0; b < 2; ++b) {
                int m0r = n0 + rloc0 + b * 16;
                #pragma unroll
                for (int nn = 0; nn < 4; ++nn) {
                    int c = cb + nn * 8;
                    if (m0r < Ncap)
                        *(float2*)(obase + (size_t)m0r * OROW + c) =
                            make_float2(acc[b][nn][0], acc[b][nn][1]);
                    if (m0r + 8 < Ncap)
                        *(float2*)(obase + (size_t)(m0r + 8) * OROW + c) =
                            make_float2(acc[b][nn][2], acc[b][nn][3]);
                }
            }
        } else {
            #pragma unroll
            for (int b = 0; b < 2; ++b)
                #pragma unroll
                for (int nn = 0; nn < 4; ++nn) {
                    int c = cb + nn * 8;
                    uint32_t a;
                    a = (uint32_t)(fr[b][0] + c * DL) * 4;       a ^= ((a >> 9) & 7u) << 4;
                    *(float*)(smem + CSOFF + a) = acc[b][nn][0];
                    a = (uint32_t)(fr[b][0] + (c + 1) * DL) * 4; a ^= ((a >> 9) & 7u) << 4;
                    *(float*)(smem + CSOFF + a) = acc[b][nn][1];
                    a = (uint32_t)(fr[b][1] + c * DL) * 4;       a ^= ((a >> 9) & 7u) << 4;
                    *(float*)(smem + CSOFF + a) = acc[b][nn][2];
                    a = (uint32_t)(fr[b][1] + (c + 1) * DL) * 4; a ^= ((a >> 9) & 7u) << 4;
                    *(float*)(smem + CSOFF + a) = acc[b][nn][3];
                }
            __syncthreads();
            #pragma unroll
            for (int k = 0; k < RP; ++k) {
                int q = tid + k * THREADS;
                int nr = q / SP4;
                int rm4 = q - nr * SP4;
                if (n0 + nr < Ncap) {
                    uint32_t a = 16u * (uint32_t)q;
                    a ^= ((a >> 9) & 7u) << 4;
                    float4 v = *(const float4*)(smem + CSOFF + a);
                    *(float4*)(obase + (size_t)(n0 + nr) * OROW + rm4 * 4) = v;
                }
            }
        }
        buf ^= 1;
    }
}

extern "C" void kernel_launch(void* const* d_in, const int* in_sizes, int n_in,
                              void* d_out, int out_size) {
    const float* x  = (const float*)d_in[0];
    const float* W0 = (const float*)d_in[1];
    const float* W1 = (const float*)d_in[2];
    const float* W2 = (const float*)d_in[3];
    float* out = (float*)d_out;

    const int N = in_sizes[0] / XROW;   // 100000

    constexpr int S1 = 2 * 64 * 128;                   // 16384 (W aliases bufs)
    constexpr int S3 = 2 * 96 * 128 + 96 * 64 * 4;     // 49152
    constexpr int S5 = 2 * 160 * 128 + 160 * 64 * 4;   // 81920

    cudaFuncSetAttribute(tp9<1, 64, 128, 3>,
                         cudaFuncAttributeMaxDynamicSharedMemorySize, S1);
    cudaFuncSetAttribute(tp9<3, 32, 64, 3>,
                         cudaFuncAttributeMaxDynamicSharedMemorySize, S3);
    cudaFuncSetAttribute(tp9<5, 32, 64, 2>,
                         cudaFuncAttributeMaxDynamicSharedMemorySize, S5);

    __half* a0p = nullptr; cudaGetSymbolAddress((void**)&a0p, g_A0);
    __half* a1p = nullptr; cudaGetSymbolAddress((void**)&a1p, g_A1);
    __half* a2p = nullptr; cudaGetSymbolAddress((void**)&a2p, g_A2);

    pre_all<<<6250 + 64, 256>>>(x, W0, W1, W2);

    const int T0 = (N + 63) / 64;   // 1563
    const int T1 = (N + 31) / 32;   // 3125
    const int T2 = (N + 31) / 32;   // 3125

    // order so ncu (-s 5 -c 1) captures tp9<5> on the 2nd replay
    tp9<5, 32, 64, 2><<<296, 320, S5>>>(a2p, out, 1024, N, T2);
    tp9<3, 32, 64, 3><<<296, 192, S3>>>(a1p, out,  256, N, T1);
    tp9<1, 64, 128, 3><<<296, 256, S1>>>(a0p, out,    0, N, T0);
}